// round 12
// baseline (speedup 1.0000x reference)
#include <cuda_runtime.h>

// ---------------- problem constants ----------------
#define BATCH 1024
#define C0_ 512
#define C1_ 1024
#define K0_ 100
#define K1_ 50
#define KP0 128
#define KP1 64
#define ROWS0 (BATCH*C0_)   // 524288
#define ROWS1 (BATCH*C1_)   // 1048576

#define MB 16
#define CC 64
#define PITCH0 133          // odd: conflict-free transposed STS + LDS
#define PITCH1 69

// ---------------- scratch (reset at end of each run; static init = zeros) --
__device__ float    g_pooled0[ROWS0];
__device__ float    g_pooled1[ROWS1];
__device__ float    g_accum[4] = {0.f, 0.f, 0.f, 0.f};
__device__ unsigned g_done = 0u;

// ---------------- pool0: warp per (b,c) row (R10-proven, at ceiling) -------
#define NB0 ((ROWS0*32)/256)    // 65536
__global__ void __launch_bounds__(256)
pool0_kernel(const float* __restrict__ feat0) {
    const unsigned wid  = (blockIdx.x * 256u + threadIdx.x) >> 5;
    const unsigned lane = threadIdx.x & 31u;
    const float4* src = reinterpret_cast<const float4*>(feat0) + (size_t)wid * 49;
    float4 a = __ldcs(src + lane);
    float  s = (a.x + a.y) + (a.z + a.w);
    if (lane < 17u) {
        float4 c = __ldcs(src + 32u + lane);
        s += (c.x + c.y) + (c.z + c.w);
    }
    #pragma unroll
    for (int o = 16; o; o >>= 1) s += __shfl_xor_sync(0xffffffffu, s, o);
    if (lane == 0u) g_pooled0[wid] = s * (1.0f / 196.0f);
}

// ---------------- pool1: 128-row smem tiles (R10-proven) -------------------
#define P1_RPB 128
#define P1_FLT (P1_RPB*49)      // 6272
#define P1_VEC (P1_FLT/4)       // 1568
#define NB1 (ROWS1/P1_RPB)      // 8192
__global__ void __launch_bounds__(256)
pool1_kernel(const float* __restrict__ feat1) {
    __shared__ float sf[P1_FLT];
    const unsigned blk = blockIdx.x;
    const float4* src = reinterpret_cast<const float4*>(feat1) + (size_t)blk * P1_VEC;
    float4* dst = reinterpret_cast<float4*>(sf);
    #pragma unroll 4
    for (int i = threadIdx.x; i < P1_VEC; i += 256)
        dst[i] = __ldcs(src + i);
    __syncthreads();
    const int t = threadIdx.x;
    if (t < P1_RPB) {
        const float* r = sf + t * 49;
        float s0 = 0.f, s1 = 0.f, s2 = 0.f, s3 = 0.f;
        #pragma unroll
        for (int e = 0; e < 48; e += 4) {
            s0 += r[e]; s1 += r[e+1]; s2 += r[e+2]; s3 += r[e+3];
        }
        g_pooled1[(size_t)blk * P1_RPB + t] =
            ((s0 + s1) + (s2 + s3) + r[48]) * (1.0f / 49.0f);
    }
}

// ---------------- head tile (R10-proven: 512 thr, pipelined W tiles) -------
#define HEAD_SMEM0 (4*(MB*C0_ + 2*CC*PITCH0 + MB*PITCH0))   // 109376
#define HEAD_SMEM1 (4*(MB*C1_ + 2*CC*PITCH1 + MB*PITCH1))   // 105280

template<int C, int K, int KPAD, int TK, int PITCH, int AOFF>
__device__ __forceinline__ void head_tile(
    const float* __restrict__ pooled,
    const float* __restrict__ W, const float* __restrict__ bias,
    const int* __restrict__ lut, const float* __restrict__ cw,
    const int* __restrict__ target, int m0, char* sraw)
{
    float* sp = reinterpret_cast<float*>(sraw);                       // [MB*C]
    float (*swt)[CC][PITCH] =
        reinterpret_cast<float(*)[CC][PITCH]>(sraw + 4*MB*C);
    float (*slg)[PITCH] =
        reinterpret_cast<float(*)[PITCH]>(sraw + 4*(MB*C + 2*CC*PITCH));

    const int tid = threadIdx.x;

    // stage pooled tile once: contiguous MB*C floats
    {
        const float4* src = reinterpret_cast<const float4*>(pooled + (size_t)m0 * C);
        float4* dst = reinterpret_cast<float4*>(sp);
        #pragma unroll
        for (int i = tid; i < MB * C / 4; i += 512) dst[i] = src[i];
    }

    constexpr int NLD = KPAD * CC / 512;   // 16 (head0) / 8 (head1)
    float ld[NLD];

    // prologue: W tile 0
    #pragma unroll
    for (int j = 0; j < NLD; j++) {
        const int idx = tid + j * 512;
        const int c = idx & (CC - 1), k = idx >> 6;
        ld[j] = (k < K) ? W[(size_t)k * C + c] : 0.0f;
    }
    #pragma unroll
    for (int j = 0; j < NLD; j++) {
        const int idx = tid + j * 512;
        swt[0][idx & (CC - 1)][idx >> 6] = ld[j];
    }
    __syncthreads();

    const int ktg = tid & 63;
    const int bt  = tid >> 6;     // 8 b-groups x 2 rows
    float acc[2][TK];
    #pragma unroll
    for (int j = 0; j < 2; j++)
        #pragma unroll
        for (int t = 0; t < TK; t++) acc[j][t] = 0.0f;

    constexpr int NCH = C / CC;
    #pragma unroll 1
    for (int ch = 0; ch < NCH; ch++) {
        if (ch + 1 < NCH) {
            const int c0 = (ch + 1) * CC;
            #pragma unroll
            for (int j = 0; j < NLD; j++) {
                const int idx = tid + j * 512;
                const int c = idx & (CC - 1), k = idx >> 6;
                ld[j] = (k < K) ? W[(size_t)k * C + c0 + c] : 0.0f;
            }
        }
        const float* sp0 = sp + (bt * 2 + 0) * C + ch * CC;
        const float* sp1 = sp + (bt * 2 + 1) * C + ch * CC;
        const float (*wt)[PITCH] = swt[ch & 1];
        #pragma unroll
        for (int c = 0; c < CC; c++) {
            const float p0 = sp0[c], p1 = sp1[c];
            if (TK == 2) {
                const float w0 = wt[c][ktg];
                const float w1 = wt[c][ktg + 64];
                acc[0][0] = fmaf(p0, w0, acc[0][0]);
                acc[0][1] = fmaf(p0, w1, acc[0][1]);
                acc[1][0] = fmaf(p1, w0, acc[1][0]);
                acc[1][1] = fmaf(p1, w1, acc[1][1]);
            } else {
                const float w0 = wt[c][ktg];
                acc[0][0] = fmaf(p0, w0, acc[0][0]);
                acc[1][0] = fmaf(p1, w0, acc[1][0]);
            }
        }
        if (ch + 1 < NCH) {
            #pragma unroll
            for (int j = 0; j < NLD; j++) {
                const int idx = tid + j * 512;
                swt[(ch + 1) & 1][idx & (CC - 1)][idx >> 6] = ld[j];
            }
        }
        __syncthreads();
    }

    #pragma unroll
    for (int t = 0; t < TK; t++) {
        const int k = ktg + t * 64;
        const float bv = (k < K) ? bias[k] : 0.0f;
        slg[bt * 2 + 0][k] = acc[0][t] + bv;
        slg[bt * 2 + 1][k] = acc[1][t] + bv;
    }
    __syncthreads();

    const int w = tid >> 5, lane = tid & 31;
    {
        float m = -3.4e38f;
        for (int k = lane; k < K; k += 32) m = fmaxf(m, slg[w][k]);
        #pragma unroll
        for (int o = 16; o; o >>= 1) m = fmaxf(m, __shfl_xor_sync(0xffffffffu, m, o));
        float s = 0.0f;
        for (int k = lane; k < K; k += 32) s += __expf(slg[w][k] - m);
        #pragma unroll
        for (int o = 16; o; o >>= 1) s += __shfl_xor_sync(0xffffffffu, s, o);
        if (lane == 0) {
            const int t = lut[target[m0 + w]];
            const float nll = m + __logf(s) - slg[w][t];
            const float wt  = cw[t];
            atomicAdd(&g_accum[AOFF],     wt * nll);
            atomicAdd(&g_accum[AOFF + 1], wt);
        }
    }
}

// shared finalize tail: counts 128 blocks across BOTH head kernels
__device__ __forceinline__ void finalize_tail(float* __restrict__ out) {
    if (threadIdx.x == 0) {
        __threadfence();
        const unsigned arrived = atomicAdd(&g_done, 1u);
        if (arrived == 127u) {
            const float n0 = atomicAdd(&g_accum[0], 0.0f);
            const float d0 = atomicAdd(&g_accum[1], 0.0f);
            const float n1 = atomicAdd(&g_accum[2], 0.0f);
            const float d1 = atomicAdd(&g_accum[3], 0.0f);
            out[0] = n0 / d0 + n1 / d1;
            #pragma unroll
            for (int i = 0; i < 4; i++) atomicExch(&g_accum[i], 0.0f);
            __threadfence();
            atomicExch(&g_done, 0u);
        }
    }
}

__global__ void __launch_bounds__(512)
heads0_kernel(const float* __restrict__ W0, const float* __restrict__ b0v,
              const int* __restrict__ lut0, const float* __restrict__ cw0,
              const int* __restrict__ target, float* __restrict__ out)
{
    extern __shared__ __align__(16) char sraw[];
    head_tile<C0_, K0_, KP0, 2, PITCH0, 0>(
        g_pooled0, W0, b0v, lut0, cw0, target, blockIdx.x * MB, sraw);
    finalize_tail(out);
}

__global__ void __launch_bounds__(512)
heads1_kernel(const float* __restrict__ W1, const float* __restrict__ b1v,
              const int* __restrict__ lut1, const float* __restrict__ cw1,
              const int* __restrict__ target, float* __restrict__ out)
{
    extern __shared__ __align__(16) char sraw[];
    head_tile<C1_, K1_, KP1, 1, PITCH1, 2>(
        g_pooled1, W1, b1v, lut1, cw1, target, blockIdx.x * MB, sraw);
    finalize_tail(out);
}

// ---------------- launch: two graph branches --------------------------------
// legacy stream: pool1 -> heads1 ; forked stream: pool0 -> heads0 ; join.
extern "C" void kernel_launch(void* const* d_in, const int* in_sizes, int n_in,
                              void* d_out, int out_size) {
    (void)in_sizes; (void)n_in; (void)out_size;
    const float* feat0  = (const float*)d_in[0];
    const float* feat1  = (const float*)d_in[1];
    const float* W0     = (const float*)d_in[2];
    const float* b0v    = (const float*)d_in[3];
    const float* W1     = (const float*)d_in[4];
    const float* b1v    = (const float*)d_in[5];
    const int*   lut0   = (const int*)d_in[6];
    const int*   lut1   = (const int*)d_in[7];
    const float* cw0    = (const float*)d_in[8];
    const float* cw1    = (const float*)d_in[9];
    const int*   target = (const int*)d_in[10];
    float* out = (float*)d_out;

    cudaFuncSetAttribute(heads0_kernel,
                         cudaFuncAttributeMaxDynamicSharedMemorySize, HEAD_SMEM0);
    cudaFuncSetAttribute(heads1_kernel,
                         cudaFuncAttributeMaxDynamicSharedMemorySize, HEAD_SMEM1);

    cudaStream_t s2;
    cudaStreamCreateWithFlags(&s2, cudaStreamNonBlocking);
    cudaEvent_t e1, e2;
    cudaEventCreateWithFlags(&e1, cudaEventDisableTiming);
    cudaEventCreateWithFlags(&e2, cudaEventDisableTiming);

    // fork: branch stream joins the capture DAG via event edge
    cudaEventRecord(e1, 0);
    cudaStreamWaitEvent(s2, e1, 0);

    // legacy branch: big pool first (hogs the machine), then its head
    pool1_kernel<<<NB1, 256>>>(feat1);
    // forked branch: small pool + its head (head0 hides under pool1 tail)
    pool0_kernel<<<NB0, 256, 0, s2>>>(feat0);
    heads0_kernel<<<BATCH / MB / 1, 512, HEAD_SMEM0, s2>>>(
        W0, b0v, lut0, cw0, target, out);
    heads1_kernel<<<BATCH / MB, 512, HEAD_SMEM1>>>(
        W1, b1v, lut1, cw1, target, out);

    // join branch back into the capture origin
    cudaEventRecord(e2, s2);
    cudaStreamWaitEvent(0, e2, 0);

    cudaEventDestroy(e1);
    cudaEventDestroy(e2);
    cudaStreamDestroy(s2);
}

// round 13
// speedup vs baseline: 1.0984x; 1.0984x over previous
#include <cuda_runtime.h>

// ---------------- problem constants ----------------
#define BATCH 1024
#define C0_ 512
#define C1_ 1024
#define K0_ 100
#define K1_ 50
#define KP0 128
#define KP1 64
#define ROWS0 (BATCH*C0_)   // 524288
#define ROWS1 (BATCH*C1_)   // 1048576

#define MB 16
#define CC 64
#define PITCH0 132
#define PITCH1 68
#define NT (BATCH/MB)       // 64 tiles per head
#define CS0 4               // head0 C-splits (128 chan each)
#define CS1 8               // head1 C-splits (128 chan each)
#define NGB (NT*CS0 + NT*CS1)   // 768 gemm blocks

// ---------------- device state (zero-init; CE kernel resets for replay) ----
__device__ float    g_pooled0[ROWS0];
__device__ float    g_pooled1[ROWS1];
__device__ float    g_logits0[BATCH*K0_];
__device__ float    g_logits1[BATCH*K1_];
__device__ float    g_accum[4] = {0.f, 0.f, 0.f, 0.f};
__device__ unsigned g_done = 0u;

// ---------------- fused pooling (R10-proven, at HBM ceiling) ----------------
#define NB0 ((ROWS0*32)/256)    // 65536
#define P1_RPB 128
#define P1_FLT (P1_RPB*49)      // 6272
#define P1_VEC (P1_FLT/4)       // 1568
#define NB1 (ROWS1/P1_RPB)      // 8192

__global__ void __launch_bounds__(256)
pool_kernel(const float* __restrict__ feat0, const float* __restrict__ feat1) {
    __shared__ float sf[P1_FLT];
    if (blockIdx.x == 0 && threadIdx.x < 5) {
        if (threadIdx.x < 4) g_accum[threadIdx.x] = 0.0f;
        else g_done = 0u;
    }
    if (blockIdx.x < NB0) {
        const unsigned wid  = (blockIdx.x * 256u + threadIdx.x) >> 5;
        const unsigned lane = threadIdx.x & 31u;
        const float4* src = reinterpret_cast<const float4*>(feat0) + (size_t)wid * 49;
        float4 a = __ldcs(src + lane);
        float  s = (a.x + a.y) + (a.z + a.w);
        if (lane < 17u) {
            float4 c = __ldcs(src + 32u + lane);
            s += (c.x + c.y) + (c.z + c.w);
        }
        #pragma unroll
        for (int o = 16; o; o >>= 1) s += __shfl_xor_sync(0xffffffffu, s, o);
        if (lane == 0u) g_pooled0[wid] = s * (1.0f / 196.0f);
    } else {
        const unsigned blk = blockIdx.x - NB0;
        const float4* src = reinterpret_cast<const float4*>(feat1) + (size_t)blk * P1_VEC;
        float4* dst = reinterpret_cast<float4*>(sf);
        #pragma unroll 4
        for (int i = threadIdx.x; i < P1_VEC; i += 256)
            dst[i] = __ldcs(src + i);
        __syncthreads();
        const int t = threadIdx.x;
        if (t < P1_RPB) {
            const float* r = sf + t * 49;
            float s0 = 0.f, s1 = 0.f, s2 = 0.f, s3 = 0.f;
            #pragma unroll
            for (int e = 0; e < 48; e += 4) {
                s0 += r[e]; s1 += r[e+1]; s2 += r[e+2]; s3 += r[e+3];
            }
            g_pooled1[(size_t)blk * P1_RPB + t] =
                ((s0 + s1) + (s2 + s3) + r[48]) * (1.0f / 49.0f);
        }
    }
}

// ---------------- split-C partial GEMM (R4 tile loop over 128 channels) ----
// Each block: MB=16 rows x full K x 128 channels; atomicAdd partial logits.
template<int C, int K, int KPAD, int TK, int PITCH>
__device__ __forceinline__ void gemm_part(
    const float* __restrict__ pooled, const float* __restrict__ W,
    float* __restrict__ logits, int m0, int cbase, char* sraw)
{
    float (*sp)[CC]     = reinterpret_cast<float(*)[CC]>(sraw);
    float (*swt)[PITCH] = reinterpret_cast<float(*)[PITCH]>(sraw + 4*MB*CC);

    const int tid = threadIdx.x;
    const int ktg = tid & 63;
    const int bt  = tid >> 6;

    float acc[4][TK];
    #pragma unroll
    for (int j = 0; j < 4; j++)
        #pragma unroll
        for (int t = 0; t < TK; t++) acc[j][t] = 0.0f;

    #pragma unroll
    for (int cc0 = 0; cc0 < 128; cc0 += CC) {
        const int c0 = cbase + cc0;
        {
            const int row = tid >> 4;
            const int c4  = tid & 15;
            float4 v = *reinterpret_cast<const float4*>(
                pooled + (size_t)(m0 + row) * C + c0 + c4 * 4);
            *reinterpret_cast<float4*>(&sp[row][c4 * 4]) = v;
        }
        #pragma unroll
        for (int idx = tid; idx < KPAD * CC; idx += 256) {
            const int c = idx & (CC - 1);
            const int k = idx >> 6;
            swt[c][k] = (k < K) ? W[(size_t)k * C + c0 + c] : 0.0f;
        }
        __syncthreads();

        #pragma unroll 4
        for (int c4 = 0; c4 < CC / 4; c4++) {
            float pv[4][4];
            #pragma unroll
            for (int j = 0; j < 4; j++) {
                float4 v = *reinterpret_cast<const float4*>(&sp[bt * 4 + j][c4 * 4]);
                pv[j][0] = v.x; pv[j][1] = v.y; pv[j][2] = v.z; pv[j][3] = v.w;
            }
            #pragma unroll
            for (int cc = 0; cc < 4; cc++) {
                const int c = c4 * 4 + cc;
                if (TK == 2) {
                    float2 wv = *reinterpret_cast<const float2*>(&swt[c][ktg * 2]);
                    #pragma unroll
                    for (int j = 0; j < 4; j++) {
                        acc[j][0] = fmaf(pv[j][cc], wv.x, acc[j][0]);
                        acc[j][1] = fmaf(pv[j][cc], wv.y, acc[j][1]);
                    }
                } else {
                    float wv = swt[c][ktg];
                    #pragma unroll
                    for (int j = 0; j < 4; j++)
                        acc[j][0] = fmaf(pv[j][cc], wv, acc[j][0]);
                }
            }
        }
        __syncthreads();
    }

    // accumulate partial logits (spread-address float atomics)
    #pragma unroll
    for (int t = 0; t < TK; t++) {
        const int k = ktg * TK + t;
        if (k < K) {
            #pragma unroll
            for (int j = 0; j < 4; j++)
                atomicAdd(&logits[(size_t)(m0 + bt * 4 + j) * K + k], acc[j][t]);
        }
    }
}

__global__ void __launch_bounds__(256)
gemm_kernel(const float* __restrict__ W0, const float* __restrict__ W1)
{
    __shared__ __align__(16) char sraw[4*MB*CC + 4*CC*PITCH0];   // 37888 B
    const unsigned bx = blockIdx.x;
    if (bx < NT * CS0) {
        const int tile = bx >> 2, cs = bx & 3;
        gemm_part<C0_, K0_, KP0, 2, PITCH0>(
            g_pooled0, W0, g_logits0, tile * MB, cs * 128, sraw);
    } else {
        const unsigned q = bx - NT * CS0;
        const int tile = q >> 3, cs = q & 7;
        gemm_part<C1_, K1_, KP1, 1, PITCH1>(
            g_pooled1, W1, g_logits1, tile * MB, cs * 128, sraw);
    }
}

// ---------------- CE kernel: warp per row; finalize + reset ----------------
__device__ __forceinline__ void ce_row(
    float* __restrict__ logits, const float* __restrict__ bias, int K,
    const int* __restrict__ lut, const float* __restrict__ cw,
    const int* __restrict__ target, int b, int aoff)
{
    const int lane = threadIdx.x & 31;
    const int niter = (K + 31) >> 5;
    float vals[4];
    float m = -3.4e38f;
    #pragma unroll
    for (int i = 0; i < 4; i++) {
        if (i < niter) {
            const int k = lane + i * 32;
            const float v = (k < K) ? logits[(size_t)b * K + k] + bias[k] : -3.4e38f;
            vals[i] = v;
            m = fmaxf(m, v);
        }
    }
    #pragma unroll
    for (int o = 16; o; o >>= 1) m = fmaxf(m, __shfl_xor_sync(0xffffffffu, m, o));
    float s = 0.0f;
    #pragma unroll
    for (int i = 0; i < 4; i++) {
        if (i < niter) {
            const int k = lane + i * 32;
            if (k < K) s += __expf(vals[i] - m);
        }
    }
    #pragma unroll
    for (int o = 16; o; o >>= 1) s += __shfl_xor_sync(0xffffffffu, s, o);

    const int t = lut[target[b]];
    const float tv = __shfl_sync(0xffffffffu, vals[t >> 5], t & 31);
    if (lane == 0) {
        const float nll = m + __logf(s) - tv;
        const float wt  = cw[t];
        atomicAdd(&g_accum[aoff],     wt * nll);
        atomicAdd(&g_accum[aoff + 1], wt);
    }
    // reset logits for the next graph replay
    #pragma unroll
    for (int i = 0; i < 4; i++) {
        if (i < niter) {
            const int k = lane + i * 32;
            if (k < K) logits[(size_t)b * K + k] = 0.0f;
        }
    }
}

#define CE_BLOCKS 64
__global__ void __launch_bounds__(256)
ce_kernel(const float* __restrict__ b0v, const float* __restrict__ b1v,
          const int* __restrict__ lut0, const int* __restrict__ lut1,
          const float* __restrict__ cw0, const float* __restrict__ cw1,
          const int* __restrict__ target, float* __restrict__ out)
{
    const int gw = (blockIdx.x * 256 + threadIdx.x) >> 5;   // 512 warps
    #pragma unroll
    for (int j = 0; j < 4; j++) {
        const int r = gw * 4 + j;                           // 2048 rows
        if (r < BATCH)
            ce_row(g_logits0, b0v, K0_, lut0, cw0, target, r, 0);
        else
            ce_row(g_logits1, b1v, K1_, lut1, cw1, target, r - BATCH, 2);
    }
    __syncthreads();
    if (threadIdx.x == 0) {
        __threadfence();
        const unsigned arrived = atomicAdd(&g_done, 1u);
        if (arrived == CE_BLOCKS - 1u) {
            const float n0 = atomicAdd(&g_accum[0], 0.0f);
            const float d0 = atomicAdd(&g_accum[1], 0.0f);
            const float n1 = atomicAdd(&g_accum[2], 0.0f);
            const float d1 = atomicAdd(&g_accum[3], 0.0f);
            out[0] = n0 / d0 + n1 / d1;
            #pragma unroll
            for (int i = 0; i < 4; i++) atomicExch(&g_accum[i], 0.0f);
            __threadfence();
            atomicExch(&g_done, 0u);
        }
    }
}

// ---------------- launch ----------------
extern "C" void kernel_launch(void* const* d_in, const int* in_sizes, int n_in,
                              void* d_out, int out_size) {
    (void)in_sizes; (void)n_in; (void)out_size;
    const float* feat0  = (const float*)d_in[0];
    const float* feat1  = (const float*)d_in[1];
    const float* W0     = (const float*)d_in[2];
    const float* b0v    = (const float*)d_in[3];
    const float* W1     = (const float*)d_in[4];
    const float* b1v    = (const float*)d_in[5];
    const int*   lut0   = (const int*)d_in[6];
    const int*   lut1   = (const int*)d_in[7];
    const float* cw0    = (const float*)d_in[8];
    const float* cw1    = (const float*)d_in[9];
    const int*   target = (const int*)d_in[10];
    float* out = (float*)d_out;

    pool_kernel<<<NB0 + NB1, 256>>>(feat0, feat1);
    gemm_kernel<<<NGB, 256>>>(W0, W1);
    ce_kernel<<<CE_BLOCKS, 256>>>(b0v, b1v, lut0, lut1, cw0, cw1, target, out);
}